// round 5
// baseline (speedup 1.0000x reference)
#include <cuda_runtime.h>

#define S_LEN 2048
#define NHEAD 16
#define DHEAD 64
#define BM 128
#define BN 64
#define KSTR 72   // K smem stride: 8g+2t4 bank pattern -> conflict-free LDS.64
#define VSTR 68   // V smem stride: 8t4+g bank pattern -> conflict-free LDS.32

static __device__ __forceinline__ unsigned f2tf(float x) {
    unsigned y;
    asm("cvt.rna.tf32.f32 %0, %1;" : "=r"(y) : "f"(x));
    return y;
}

static __device__ __forceinline__ void mma_tf32(float* d,
                                                unsigned a0, unsigned a1, unsigned a2, unsigned a3,
                                                unsigned b0, unsigned b1) {
    asm volatile("mma.sync.aligned.m16n8k8.row.col.f32.tf32.tf32.f32 "
                 "{%0,%1,%2,%3}, {%4,%5,%6,%7}, {%8,%9}, {%0,%1,%2,%3};"
                 : "+f"(d[0]), "+f"(d[1]), "+f"(d[2]), "+f"(d[3])
                 : "r"(a0), "r"(a1), "r"(a2), "r"(a3), "r"(b0), "r"(b1));
}

__global__ __launch_bounds__(128, 2)
void attn_tc2_kernel(const float* __restrict__ Q, const float* __restrict__ K,
                     const float* __restrict__ V, float* __restrict__ Out) {
    extern __shared__ float sm[];
    float* Ks = sm;                 // [BN][KSTR]
    float* Vs = sm + BN * KSTR;     // [BN][VSTR]

    const int qt   = (gridDim.x - 1) - blockIdx.x;   // heavy tiles first
    const int bh   = blockIdx.y;
    const int b    = bh >> 4;
    const int h    = bh & 15;
    const int qrow = qt * BM;

    const float* Kg = K + (size_t)bh * S_LEN * DHEAD;
    const float* Vg = V + (size_t)bh * S_LEN * DHEAD;

    const int tid  = threadIdx.x;
    const int warp = tid >> 5;
    const int lane = tid & 31;
    const int g    = lane >> 2;
    const int t4   = lane & 3;
    const int wrow = warp << 5;            // 32 q-rows per warp (2 slabs)
    const int row_min = qrow + wrow;

    // ---- Q fragments straight from global, pre-scaled, rna->tf32 ----
    // k-chunk ks uses d-perm: MMA k=t4 -> d=8ks+2t4, k=t4+4 -> d=8ks+2t4+1
    unsigned qa[2][8][4];
    {
        const float* Qg = Q + ((size_t)bh * S_LEN + row_min) * DHEAD;
        #pragma unroll
        for (int s2 = 0; s2 < 2; s2++)
            #pragma unroll
            for (int ks = 0; ks < 8; ks++) {
                const float* rp = Qg + (16 * s2 + g) * DHEAD + 8 * ks + 2 * t4;
                float2 q0 = *(const float2*)rp;
                float2 q1 = *(const float2*)(rp + 8 * DHEAD);
                qa[s2][ks][0] = f2tf(0.125f * q0.x);
                qa[s2][ks][2] = f2tf(0.125f * q0.y);
                qa[s2][ks][1] = f2tf(0.125f * q1.x);
                qa[s2][ks][3] = f2tf(0.125f * q1.y);
            }
    }

    float o0[8][4], o1[8][4];
    #pragma unroll
    for (int nt = 0; nt < 8; nt++)
        #pragma unroll
        for (int e = 0; e < 4; e++) { o0[nt][e] = 0.f; o1[nt][e] = 0.f; }

    float m00 = -1e30f, m01 = -1e30f, m10 = -1e30f, m11 = -1e30f;
    float l00 = 0.f, l01 = 0.f, l10 = 0.f, l11 = 0.f;

    const int kt_last = (qrow + BM - 1) >> 6;

    for (int kt = 0; kt <= kt_last; kt++) {
        // ---- Prefetch next K/V tile into regs (issued before syncs) ----
        const float* Kgt = Kg + (size_t)kt * BN * DHEAD;
        const float* Vgt = Vg + (size_t)kt * BN * DHEAD;
        float4 kr[8], vr[8];
        #pragma unroll
        for (int it = 0; it < 8; it++) {
            int i  = tid + (it << 7);
            int r  = i >> 4;
            int d4 = (i & 15) << 2;
            kr[it] = *(const float4*)(Kgt + r * DHEAD + d4);
            vr[it] = *(const float4*)(Vgt + r * DHEAD + d4);
        }
        __syncthreads();   // previous iteration's readers done
        #pragma unroll
        for (int it = 0; it < 8; it++) {
            int i  = tid + (it << 7);
            int r  = i >> 4;
            int d4 = (i & 15) << 2;
            *(float4*)(Ks + r * KSTR + d4) = make_float4(
                __uint_as_float(f2tf(kr[it].x)), __uint_as_float(f2tf(kr[it].y)),
                __uint_as_float(f2tf(kr[it].z)), __uint_as_float(f2tf(kr[it].w)));
            *(float4*)(Vs + r * VSTR + d4) = make_float4(
                __uint_as_float(f2tf(vr[it].x)), __uint_as_float(f2tf(vr[it].y)),
                __uint_as_float(f2tf(vr[it].z)), __uint_as_float(f2tf(vr[it].w)));
        }
        __syncthreads();

        // warp-uniform skip: tile entirely above this warp's rows
        if ((kt << 6) > row_min + 31) continue;

        // ---- GEMM1: S = (Q*scale) K^T ; B frag = one LDS.64, shared by 2 slabs ----
        float s0[8][4], s1[8][4];
        #pragma unroll
        for (int nt = 0; nt < 8; nt++)
            #pragma unroll
            for (int e = 0; e < 4; e++) { s0[nt][e] = 0.f; s1[nt][e] = 0.f; }

        #pragma unroll
        for (int nt = 0; nt < 8; nt++) {
            const float* kb = Ks + (g + 8 * nt) * KSTR + 2 * t4;
            #pragma unroll
            for (int ks = 0; ks < 8; ks++) {
                float2 bb = *(const float2*)(kb + 8 * ks);
                unsigned b0 = __float_as_uint(bb.x);
                unsigned b1 = __float_as_uint(bb.y);
                mma_tf32(s0[nt], qa[0][ks][0], qa[0][ks][1], qa[0][ks][2], qa[0][ks][3], b0, b1);
                mma_tf32(s1[nt], qa[1][ks][0], qa[1][ks][1], qa[1][ks][2], qa[1][ks][3], b0, b1);
            }
        }

        // ---- Causal mask (only on partial tiles) ----
        if ((kt << 6) + 63 > row_min) {
            const int colb = (kt << 6) + 2 * t4;
            const int R0 = row_min + g;
            #pragma unroll
            for (int nt = 0; nt < 8; nt++) {
                int c0 = colb + 8 * nt, c1 = c0 + 1;
                if (c0 > R0)      s0[nt][0] = -10000.0f;
                if (c1 > R0)      s0[nt][1] = -10000.0f;
                if (c0 > R0 + 8)  s0[nt][2] = -10000.0f;
                if (c1 > R0 + 8)  s0[nt][3] = -10000.0f;
                if (c0 > R0 + 16) s1[nt][0] = -10000.0f;
                if (c1 > R0 + 16) s1[nt][1] = -10000.0f;
                if (c0 > R0 + 24) s1[nt][2] = -10000.0f;
                if (c1 > R0 + 24) s1[nt][3] = -10000.0f;
            }
        }

        // ---- Online softmax, slab 0 ----
        {
            float mx0 = -1e30f, mx1 = -1e30f;
            #pragma unroll
            for (int nt = 0; nt < 8; nt++) {
                mx0 = fmaxf(mx0, fmaxf(s0[nt][0], s0[nt][1]));
                mx1 = fmaxf(mx1, fmaxf(s0[nt][2], s0[nt][3]));
            }
            mx0 = fmaxf(mx0, __shfl_xor_sync(0xffffffffu, mx0, 1));
            mx0 = fmaxf(mx0, __shfl_xor_sync(0xffffffffu, mx0, 2));
            mx1 = fmaxf(mx1, __shfl_xor_sync(0xffffffffu, mx1, 1));
            mx1 = fmaxf(mx1, __shfl_xor_sync(0xffffffffu, mx1, 2));
            float mn0 = fmaxf(m00, mx0), mn1 = fmaxf(m01, mx1);
            float cr0 = __expf(m00 - mn0), cr1 = __expf(m01 - mn1);
            float sum0 = 0.f, sum1 = 0.f;
            #pragma unroll
            for (int nt = 0; nt < 8; nt++) {
                float p0 = __expf(s0[nt][0] - mn0);
                float p1 = __expf(s0[nt][1] - mn0);
                float p2 = __expf(s0[nt][2] - mn1);
                float p3 = __expf(s0[nt][3] - mn1);
                sum0 += p0 + p1; sum1 += p2 + p3;
                s0[nt][0] = __uint_as_float(f2tf(p0));   // P stays in regs as tf32
                s0[nt][1] = __uint_as_float(f2tf(p1));
                s0[nt][2] = __uint_as_float(f2tf(p2));
                s0[nt][3] = __uint_as_float(f2tf(p3));
            }
            sum0 += __shfl_xor_sync(0xffffffffu, sum0, 1);
            sum0 += __shfl_xor_sync(0xffffffffu, sum0, 2);
            sum1 += __shfl_xor_sync(0xffffffffu, sum1, 1);
            sum1 += __shfl_xor_sync(0xffffffffu, sum1, 2);
            l00 = l00 * cr0 + sum0; l01 = l01 * cr1 + sum1;
            m00 = mn0; m01 = mn1;
            #pragma unroll
            for (int nt = 0; nt < 8; nt++) {
                o0[nt][0] *= cr0; o0[nt][1] *= cr0;
                o0[nt][2] *= cr1; o0[nt][3] *= cr1;
            }
        }
        // ---- Online softmax, slab 1 ----
        {
            float mx0 = -1e30f, mx1 = -1e30f;
            #pragma unroll
            for (int nt = 0; nt < 8; nt++) {
                mx0 = fmaxf(mx0, fmaxf(s1[nt][0], s1[nt][1]));
                mx1 = fmaxf(mx1, fmaxf(s1[nt][2], s1[nt][3]));
            }
            mx0 = fmaxf(mx0, __shfl_xor_sync(0xffffffffu, mx0, 1));
            mx0 = fmaxf(mx0, __shfl_xor_sync(0xffffffffu, mx0, 2));
            mx1 = fmaxf(mx1, __shfl_xor_sync(0xffffffffu, mx1, 1));
            mx1 = fmaxf(mx1, __shfl_xor_sync(0xffffffffu, mx1, 2));
            float mn0 = fmaxf(m10, mx0), mn1 = fmaxf(m11, mx1);
            float cr0 = __expf(m10 - mn0), cr1 = __expf(m11 - mn1);
            float sum0 = 0.f, sum1 = 0.f;
            #pragma unroll
            for (int nt = 0; nt < 8; nt++) {
                float p0 = __expf(s1[nt][0] - mn0);
                float p1 = __expf(s1[nt][1] - mn0);
                float p2 = __expf(s1[nt][2] - mn1);
                float p3 = __expf(s1[nt][3] - mn1);
                sum0 += p0 + p1; sum1 += p2 + p3;
                s1[nt][0] = __uint_as_float(f2tf(p0));
                s1[nt][1] = __uint_as_float(f2tf(p1));
                s1[nt][2] = __uint_as_float(f2tf(p2));
                s1[nt][3] = __uint_as_float(f2tf(p3));
            }
            sum0 += __shfl_xor_sync(0xffffffffu, sum0, 1);
            sum0 += __shfl_xor_sync(0xffffffffu, sum0, 2);
            sum1 += __shfl_xor_sync(0xffffffffu, sum1, 1);
            sum1 += __shfl_xor_sync(0xffffffffu, sum1, 2);
            l10 = l10 * cr0 + sum0; l11 = l11 * cr1 + sum1;
            m10 = mn0; m11 = mn1;
            #pragma unroll
            for (int nt = 0; nt < 8; nt++) {
                o1[nt][0] *= cr0; o1[nt][1] *= cr0;
                o1[nt][2] *= cr1; o1[nt][3] *= cr1;
            }
        }

        // ---- GEMM2: O += P V.  A = GEMM1 C-frags (perm trick), B shared by slabs ----
        #pragma unroll
        for (int nt = 0; nt < 8; nt++) {
            const float* vb = Vs + g + 8 * nt;
            #pragma unroll
            for (int ks = 0; ks < 8; ks++) {
                const float* vp = vb + (8 * ks + 2 * t4) * VSTR;
                unsigned b0 = __float_as_uint(vp[0]);
                unsigned b1 = __float_as_uint(vp[VSTR]);
                // A frag = (c0, c2, c1, c3)
                mma_tf32(o0[nt],
                         __float_as_uint(s0[ks][0]), __float_as_uint(s0[ks][2]),
                         __float_as_uint(s0[ks][1]), __float_as_uint(s0[ks][3]), b0, b1);
                mma_tf32(o1[nt],
                         __float_as_uint(s1[ks][0]), __float_as_uint(s1[ks][2]),
                         __float_as_uint(s1[ks][1]), __float_as_uint(s1[ks][3]), b0, b1);
            }
        }
    }

    // ---- Epilogue ----
    const float i00 = 1.f / l00, i01 = 1.f / l01;
    const float i10 = 1.f / l10, i11 = 1.f / l11;
    const int R0 = row_min + g;
    float* Ob = Out + (size_t)b * S_LEN * (NHEAD * DHEAD) + h * DHEAD;
    float* Op0 = Ob + (size_t)(R0)      * (NHEAD * DHEAD);
    float* Op1 = Ob + (size_t)(R0 + 8)  * (NHEAD * DHEAD);
    float* Op2 = Ob + (size_t)(R0 + 16) * (NHEAD * DHEAD);
    float* Op3 = Ob + (size_t)(R0 + 24) * (NHEAD * DHEAD);
    #pragma unroll
    for (int nt = 0; nt < 8; nt++) {
        int col = 8 * nt + 2 * t4;
        *(float2*)(Op0 + col) = make_float2(o0[nt][0] * i00, o0[nt][1] * i00);
        *(float2*)(Op1 + col) = make_float2(o0[nt][2] * i01, o0[nt][3] * i01);
        *(float2*)(Op2 + col) = make_float2(o1[nt][0] * i10, o1[nt][1] * i10);
        *(float2*)(Op3 + col) = make_float2(o1[nt][2] * i11, o1[nt][3] * i11);
    }
}

extern "C" void kernel_launch(void* const* d_in, const int* in_sizes, int n_in,
                              void* d_out, int out_size) {
    (void)in_sizes; (void)n_in; (void)out_size;
    const float* q = (const float*)d_in[0];
    const float* k = (const float*)d_in[1];
    const float* v = (const float*)d_in[2];
    float* out = (float*)d_out;

    const int smem_bytes = (BN * KSTR + BN * VSTR) * (int)sizeof(float);  // 35840 B
    cudaFuncSetAttribute(attn_tc2_kernel,
                         cudaFuncAttributeMaxDynamicSharedMemorySize, smem_bytes);

    dim3 grid(S_LEN / BM, 4 * NHEAD);   // (16, 64)
    attn_tc2_kernel<<<grid, 128, smem_bytes>>>(q, k, v, out);
}

// round 6
// speedup vs baseline: 1.6553x; 1.6553x over previous
#include <cuda_runtime.h>

#define S_LEN 2048
#define NHEAD 16
#define DHEAD 64
#define BM 64
#define BN 64
#define KSTR 72   // K smem stride: conflict-free LDS.64 B-frags (bank 8g+2t4)
#define VSTR 68   // V smem stride: conflict-free scalar B-frags (bank 8t4+g)

static __device__ __forceinline__ unsigned f2tf(float x) {
    unsigned y;
    asm("cvt.rna.tf32.f32 %0, %1;" : "=r"(y) : "f"(x));
    return y;
}

static __device__ __forceinline__ void mma_tf32(float* d,
                                                unsigned a0, unsigned a1, unsigned a2, unsigned a3,
                                                unsigned b0, unsigned b1) {
    asm volatile("mma.sync.aligned.m16n8k8.row.col.f32.tf32.tf32.f32 "
                 "{%0,%1,%2,%3}, {%4,%5,%6,%7}, {%8,%9}, {%0,%1,%2,%3};"
                 : "+f"(d[0]), "+f"(d[1]), "+f"(d[2]), "+f"(d[3])
                 : "r"(a0), "r"(a1), "r"(a2), "r"(a3), "r"(b0), "r"(b1));
}

__global__ __launch_bounds__(128, 3)
void attn_tc3_kernel(const float* __restrict__ Q, const float* __restrict__ K,
                     const float* __restrict__ V, float* __restrict__ Out) {
    extern __shared__ float sm[];
    float* Ks = sm;                 // [BN][KSTR] tf32 bits, natural [key][d]
    float* Vs = sm + BN * KSTR;     // [BN][VSTR] tf32 bits, natural [key][d]

    const int qt   = (gridDim.x - 1) - blockIdx.x;   // heavy tiles first
    const int bh   = blockIdx.y;
    const int b    = bh >> 4;
    const int h    = bh & 15;
    const int qrow = qt * BM;

    const float* Kg = K + (size_t)bh * S_LEN * DHEAD;
    const float* Vg = V + (size_t)bh * S_LEN * DHEAD;

    const int tid  = threadIdx.x;
    const int warp = tid >> 5;
    const int lane = tid & 31;
    const int g    = lane >> 2;
    const int t4   = lane & 3;
    const int r0w  = warp << 4;                 // 16 q-rows per warp
    const int row0 = qrow + r0w + g;            // thread's row (frag rows row0, row0+8)
    const int row1 = row0 + 8;

    // ---- Q A-fragments straight from global, pre-scaled, rna->tf32 ----
    // k-perm within each 8-wide chunk ks: k(t4) = 2*t4, k(t4+4) = 2*t4+1.
    unsigned qa[8][4];
    {
        const float* Qg = Q + ((size_t)bh * S_LEN + qrow + r0w) * DHEAD;
        #pragma unroll
        for (int ks = 0; ks < 8; ks++) {
            const float* rp = Qg + g * DHEAD + 8 * ks + 2 * t4;
            float2 q0 = *(const float2*)rp;                 // row g
            float2 q1 = *(const float2*)(rp + 8 * DHEAD);   // row g+8
            qa[ks][0] = f2tf(0.125f * q0.x);   // A[g][2t4]
            qa[ks][1] = f2tf(0.125f * q1.x);   // A[g+8][2t4]
            qa[ks][2] = f2tf(0.125f * q0.y);   // A[g][2t4+1]
            qa[ks][3] = f2tf(0.125f * q1.y);   // A[g+8][2t4+1]
        }
    }

    float o[8][4];
    #pragma unroll
    for (int nt = 0; nt < 8; nt++)
        #pragma unroll
        for (int e = 0; e < 4; e++) o[nt][e] = 0.f;

    float m0 = -1e30f, m1 = -1e30f, l0 = 0.f, l1 = 0.f;

    for (int kt = 0; kt <= qt; kt++) {
        // ---- Prefetch K/V tile into regs before the sync ----
        const float* Kgt = Kg + (size_t)kt * BN * DHEAD;
        const float* Vgt = Vg + (size_t)kt * BN * DHEAD;
        float4 kr[8], vr[8];
        #pragma unroll
        for (int it = 0; it < 8; it++) {
            int i  = tid + (it << 7);
            int r  = i >> 4;
            int d4 = (i & 15) << 2;
            kr[it] = *(const float4*)(Kgt + r * DHEAD + d4);
            vr[it] = *(const float4*)(Vgt + r * DHEAD + d4);
        }
        __syncthreads();   // previous iteration's Ks/Vs readers done
        #pragma unroll
        for (int it = 0; it < 8; it++) {
            int i  = tid + (it << 7);
            int r  = i >> 4;
            int d4 = (i & 15) << 2;
            *(float4*)(Ks + r * KSTR + d4) = make_float4(
                __uint_as_float(f2tf(kr[it].x)), __uint_as_float(f2tf(kr[it].y)),
                __uint_as_float(f2tf(kr[it].z)), __uint_as_float(f2tf(kr[it].w)));
            *(float4*)(Vs + r * VSTR + d4) = make_float4(
                __uint_as_float(f2tf(vr[it].x)), __uint_as_float(f2tf(vr[it].y)),
                __uint_as_float(f2tf(vr[it].z)), __uint_as_float(f2tf(vr[it].w)));
        }
        __syncthreads();

        // ---- GEMM1: S = (Q*scale) K^T. B-frag = 1 conflict-free LDS.64 ----
        float s[8][4];
        #pragma unroll
        for (int nt = 0; nt < 8; nt++) {
            s[nt][0] = 0.f; s[nt][1] = 0.f; s[nt][2] = 0.f; s[nt][3] = 0.f;
            const float* kb = Ks + (g + 8 * nt) * KSTR + 2 * t4;
            #pragma unroll
            for (int ks = 0; ks < 8; ks++) {
                float2 bb = *(const float2*)(kb + 8 * ks);   // K[g+8nt][8ks+2t4 .. +1]
                mma_tf32(s[nt], qa[ks][0], qa[ks][1], qa[ks][2], qa[ks][3],
                         __float_as_uint(bb.x), __float_as_uint(bb.y));
            }
        }

        // ---- Causal mask (diagonal tile only) ----
        if (kt == qt) {
            const int colb = (kt << 6) + 2 * t4;
            #pragma unroll
            for (int nt = 0; nt < 8; nt++) {
                int c0 = colb + 8 * nt, c1 = c0 + 1;
                if (c0 > row0) s[nt][0] = -10000.0f;   // C[g][c0]
                if (c1 > row0) s[nt][1] = -10000.0f;   // C[g][c1]
                if (c0 > row1) s[nt][2] = -10000.0f;   // C[g+8][c0]
                if (c1 > row1) s[nt][3] = -10000.0f;   // C[g+8][c1]
            }
        }

        // ---- Online softmax (rows row0 / row1), P stays in regs as tf32 ----
        float mx0 = -1e30f, mx1 = -1e30f;
        #pragma unroll
        for (int nt = 0; nt < 8; nt++) {
            mx0 = fmaxf(mx0, fmaxf(s[nt][0], s[nt][1]));
            mx1 = fmaxf(mx1, fmaxf(s[nt][2], s[nt][3]));
        }
        mx0 = fmaxf(mx0, __shfl_xor_sync(0xffffffffu, mx0, 1));
        mx0 = fmaxf(mx0, __shfl_xor_sync(0xffffffffu, mx0, 2));
        mx1 = fmaxf(mx1, __shfl_xor_sync(0xffffffffu, mx1, 1));
        mx1 = fmaxf(mx1, __shfl_xor_sync(0xffffffffu, mx1, 2));

        float mn0 = fmaxf(m0, mx0), mn1 = fmaxf(m1, mx1);
        float cr0 = __expf(m0 - mn0), cr1 = __expf(m1 - mn1);

        float sum0 = 0.f, sum1 = 0.f;
        #pragma unroll
        for (int nt = 0; nt < 8; nt++) {
            float p0 = __expf(s[nt][0] - mn0);
            float p1 = __expf(s[nt][1] - mn0);
            float p2 = __expf(s[nt][2] - mn1);
            float p3 = __expf(s[nt][3] - mn1);
            sum0 += p0 + p1; sum1 += p2 + p3;
            s[nt][0] = __uint_as_float(f2tf(p0));
            s[nt][1] = __uint_as_float(f2tf(p1));
            s[nt][2] = __uint_as_float(f2tf(p2));
            s[nt][3] = __uint_as_float(f2tf(p3));
        }
        sum0 += __shfl_xor_sync(0xffffffffu, sum0, 1);
        sum0 += __shfl_xor_sync(0xffffffffu, sum0, 2);
        sum1 += __shfl_xor_sync(0xffffffffu, sum1, 1);
        sum1 += __shfl_xor_sync(0xffffffffu, sum1, 2);

        l0 = l0 * cr0 + sum0;
        l1 = l1 * cr1 + sum1;
        m0 = mn0; m1 = mn1;

        #pragma unroll
        for (int nt = 0; nt < 8; nt++) {
            o[nt][0] *= cr0; o[nt][1] *= cr0;
            o[nt][2] *= cr1; o[nt][3] *= cr1;
        }

        // ---- GEMM2: O += P V. A = GEMM1 C-frag (perm trick: c0,c2,c1,c3). ----
        // B rows 8ks+2t4, 8ks+2t4+1 at col g+8nt: two conflict-free scalar LDS.
        #pragma unroll
        for (int ks = 0; ks < 8; ks++) {
            const float* vp = Vs + (8 * ks + 2 * t4) * VSTR + g;
            unsigned a0 = __float_as_uint(s[ks][0]);
            unsigned a1 = __float_as_uint(s[ks][2]);
            unsigned a2 = __float_as_uint(s[ks][1]);
            unsigned a3 = __float_as_uint(s[ks][3]);
            #pragma unroll
            for (int nt = 0; nt < 8; nt++) {
                unsigned b0 = __float_as_uint(vp[8 * nt]);          // V[8ks+2t4][g+8nt]
                unsigned b1 = __float_as_uint(vp[VSTR + 8 * nt]);   // V[8ks+2t4+1][g+8nt]
                mma_tf32(o[nt], a0, a1, a2, a3, b0, b1);
            }
        }
    }

    // ---- Epilogue: normalize, write Out[b][s][h*64 + d] ----
    const float inv0 = 1.f / l0;
    const float inv1 = 1.f / l1;
    float* Op0 = Out + ((size_t)b * S_LEN + row0) * (NHEAD * DHEAD) + h * DHEAD;
    float* Op1 = Out + ((size_t)b * S_LEN + row1) * (NHEAD * DHEAD) + h * DHEAD;
    #pragma unroll
    for (int nt = 0; nt < 8; nt++) {
        int col = 8 * nt + 2 * t4;
        *(float2*)(Op0 + col) = make_float2(o[nt][0] * inv0, o[nt][1] * inv0);
        *(float2*)(Op1 + col) = make_float2(o[nt][2] * inv1, o[nt][3] * inv1);
    }
}

extern "C" void kernel_launch(void* const* d_in, const int* in_sizes, int n_in,
                              void* d_out, int out_size) {
    (void)in_sizes; (void)n_in; (void)out_size;
    const float* q = (const float*)d_in[0];
    const float* k = (const float*)d_in[1];
    const float* v = (const float*)d_in[2];
    float* out = (float*)d_out;

    const int smem_bytes = (BN * KSTR + BN * VSTR) * (int)sizeof(float);  // 35840 B
    cudaFuncSetAttribute(attn_tc3_kernel,
                         cudaFuncAttributeMaxDynamicSharedMemorySize, smem_bytes);

    dim3 grid(S_LEN / BM, 4 * NHEAD);   // (32, 64)
    attn_tc3_kernel<<<grid, 128, smem_bytes>>>(q, k, v, out);
}